// round 15
// baseline (speedup 1.0000x reference)
#include <cuda_runtime.h>
#include <cuda_fp16.h>
#include <cstdint>

#define Nn 50000
#define Ee 600000
#define INC 16
#define EDC 8
#define HID 128
#define NH 4
#define CC 32
#define EMBC 64
#define EPW 8
#define FULLMASK 0xffffffffu
#define PAD 136   // halves; 272B row stride -> ldmatrix conflict-free

// ---------------- scratch (device globals) ----------------
__device__ float d_z[Nn * HID];
__device__ __half d_xlh[Nn * HID];   // fp16; includes +bl
__device__ __half d_xrh[Nn * HID];   // fp16; includes +br+be
__device__ __half d_aggh[Nn * HID];  // fp16 aggregation (red.f16x2)
__device__ float d_den[Nn * NH];

// packed f32x2 helpers
__device__ __forceinline__ unsigned long long pack2(float a) {
    unsigned long long r;
    asm("mov.b64 %0, {%1, %1};" : "=l"(r) : "r"(__float_as_uint(a)));
    return r;
}
__device__ __forceinline__ unsigned long long packxy(float x, float y) {
    unsigned long long r;
    asm("mov.b64 %0, {%1, %2};" : "=l"(r) : "r"(__float_as_uint(x)), "r"(__float_as_uint(y)));
    return r;
}
__device__ __forceinline__ void fma2(unsigned long long& d, unsigned long long a,
                                     unsigned long long b) {
    asm("fma.rn.f32x2 %0, %1, %2, %0;" : "+l"(d) : "l"(a), "l"(b));
}
__device__ __forceinline__ unsigned long long add2(unsigned long long a,
                                                   unsigned long long b) {
    unsigned long long r;
    asm("add.rn.f32x2 %0, %1, %2;" : "=l"(r) : "l"(a), "l"(b));
    return r;
}
__device__ __forceinline__ unsigned long long mul2(unsigned long long a,
                                                   unsigned long long b) {
    unsigned long long r;
    asm("mul.rn.f32x2 %0, %1, %2;" : "=l"(r) : "l"(a), "l"(b));
    return r;
}
__device__ __forceinline__ float lo32(unsigned long long v) {
    return __uint_as_float((unsigned int)v);
}
__device__ __forceinline__ float hi32(unsigned long long v) {
    return __uint_as_float((unsigned int)(v >> 32));
}
__device__ __forceinline__ void red_add_h2(__half* p, uint32_t h2) {
    asm volatile("red.global.add.noftz.f16x2 [%0], %1;"
                 :: "l"(p), "r"(h2) : "memory");
}
__device__ __forceinline__ void red_add_f(float* p, float a) {
    asm volatile("red.global.add.f32 [%0], %1;" :: "l"(p), "f"(a) : "memory");
}

// ---------------- stage 0: z = [relu(x@W_in+b_in), emb[node_idx]]; zero aggh/den ----------------
__global__ void stage0_kernel(const float* __restrict__ x,
                              const int* __restrict__ nidx,
                              const float* __restrict__ emb,
                              const float* __restrict__ Win,
                              const float* __restrict__ bin) {
    int n = blockIdx.x;
    int t = threadIdx.x;  // 128
    if (t < EMBC) {
        float a = __ldg(&bin[t]);
#pragma unroll
        for (int k = 0; k < INC; k++)
            a = fmaf(x[n * INC + k], __ldg(&Win[k * EMBC + t]), a);
        d_z[n * HID + t] = fmaxf(a, 0.0f);
    } else {
        d_z[n * HID + t] = emb[nidx[n] * EMBC + (t - EMBC)];
    }
    if (t < 64) *(uint32_t*)&d_aggh[n * HID + 2 * t] = 0u;
    if (t < NH) d_den[n * NH + t] = 0.0f;
}

// ---------------- HMMA projections: xl = z@Wl+bl, xr = z@Wr+(br+be), fp16 out ----------------
__global__ void __launch_bounds__(256) proj_mma_kernel(
    const float* __restrict__ Wl, const float* __restrict__ bl,
    const float* __restrict__ Wr, const float* __restrict__ br,
    const float* __restrict__ be) {
    extern __shared__ char smdyn[];
    __half* zs = (__half*)smdyn;                       // [64][PAD]
    __half* ws = (__half*)(smdyn + 64 * PAD * 2);      // [128][PAD]
    int t = threadIdx.x;
    int w = t >> 5, lane = t & 31;
    int base = blockIdx.x * 64;

    // fill z tile: fp32 -> fp16
#pragma unroll
    for (int i = 0; i < 32; i++) {
        int idx = i * 256 + t;
        int r = idx >> 7, c = idx & 127;
        int n = base + r;
        if (n >= Nn) n = Nn - 1;
        zs[r * PAD + c] = __float2half_rn(d_z[(size_t)n * HID + c]);
    }

    int sel15 = lane & 15;
    int sel8 = (lane >> 4) << 3;

#pragma unroll
    for (int ph = 0; ph < 2; ph++) {
        const float* W = (ph == 0) ? Wl : Wr;
        if (ph == 1) __syncthreads();
#pragma unroll
        for (int i = 0; i < 64; i++) {
            int idx = i * 256 + t;
            int k = idx >> 7, n = idx & 127;
            ws[k * PAD + n] = __float2half_rn(__ldg(&W[k * HID + n]));
        }
        __syncthreads();

        float acc[4][2][4];
#pragma unroll
        for (int mt = 0; mt < 4; mt++)
#pragma unroll
            for (int nt = 0; nt < 2; nt++)
#pragma unroll
                for (int j = 0; j < 4; j++) acc[mt][nt][j] = 0.0f;

#pragma unroll
        for (int ks = 0; ks < 8; ks++) {
            uint32_t b0, b1, b2, b3;
            {
                int krow = ks * 16 + sel15;
                int ncol = 16 * w + sel8;
                uint32_t ad = (uint32_t)__cvta_generic_to_shared(&ws[krow * PAD + ncol]);
                asm volatile("ldmatrix.sync.aligned.m8n8.x4.trans.shared.b16 {%0,%1,%2,%3}, [%4];"
                             : "=r"(b0), "=r"(b1), "=r"(b2), "=r"(b3) : "r"(ad));
            }
#pragma unroll
            for (int mt = 0; mt < 4; mt++) {
                uint32_t a0, a1, a2, a3;
                int arow = mt * 16 + sel15;
                int acol = ks * 16 + sel8;
                uint32_t ad = (uint32_t)__cvta_generic_to_shared(&zs[arow * PAD + acol]);
                asm volatile("ldmatrix.sync.aligned.m8n8.x4.shared.b16 {%0,%1,%2,%3}, [%4];"
                             : "=r"(a0), "=r"(a1), "=r"(a2), "=r"(a3) : "r"(ad));
                asm volatile("mma.sync.aligned.m16n8k16.row.col.f32.f16.f16.f32 "
                             "{%0,%1,%2,%3}, {%4,%5,%6,%7}, {%8,%9}, {%0,%1,%2,%3};"
                             : "+f"(acc[mt][0][0]), "+f"(acc[mt][0][1]),
                               "+f"(acc[mt][0][2]), "+f"(acc[mt][0][3])
                             : "r"(a0), "r"(a1), "r"(a2), "r"(a3), "r"(b0), "r"(b1));
                asm volatile("mma.sync.aligned.m16n8k16.row.col.f32.f16.f16.f32 "
                             "{%0,%1,%2,%3}, {%4,%5,%6,%7}, {%8,%9}, {%0,%1,%2,%3};"
                             : "+f"(acc[mt][1][0]), "+f"(acc[mt][1][1]),
                               "+f"(acc[mt][1][2]), "+f"(acc[mt][1][3])
                             : "r"(a0), "r"(a1), "r"(a2), "r"(a3), "r"(b2), "r"(b3));
            }
        }

        __half* dst = (ph == 0) ? d_xlh : d_xrh;
#pragma unroll
        for (int nt = 0; nt < 2; nt++) {
            int col = 16 * w + nt * 8 + (lane & 3) * 2;
            float bv0, bv1;
            if (ph == 0) {
                bv0 = __ldg(&bl[col]);
                bv1 = __ldg(&bl[col + 1]);
            } else {
                bv0 = __ldg(&br[col]) + __ldg(&be[col]);
                bv1 = __ldg(&br[col + 1]) + __ldg(&be[col + 1]);
            }
#pragma unroll
            for (int mt = 0; mt < 4; mt++) {
                int r0 = base + mt * 16 + (lane >> 2);
                int r1 = r0 + 8;
                if (r0 < Nn) {
                    __half2 v = __floats2half2_rn(acc[mt][nt][0] + bv0, acc[mt][nt][1] + bv1);
                    *(__half2*)&dst[(size_t)r0 * HID + col] = v;
                }
                if (r1 < Nn) {
                    __half2 v = __floats2half2_rn(acc[mt][nt][2] + bv0, acc[mt][nt][3] + bv1);
                    *(__half2*)&dst[(size_t)r1 * HID + col] = v;
                }
            }
        }
    }
}

// ---------------- fused edge pass: logit -> exp -> den + weighted agg (fp16 red) ----------------
__global__ void __launch_bounds__(256, 4) edge_kernel(
    const int* __restrict__ ei, const float* __restrict__ ea,
    const float* __restrict__ We, const float* __restrict__ att) {
    int l = threadIdx.x & 31;
    int warp = (blockIdx.x * blockDim.x + threadIdx.x) >> 5;
    int base = warp * EPW;
    if (base >= Ee) return;
    int h = l >> 3;

    unsigned long long w01[EDC], w23[EDC];
#pragma unroll
    for (int k = 0; k < EDC; k++) {
        ulonglong2 w = *(const ulonglong2*)&We[k * HID + 4 * l];
        w01[k] = w.x;
        w23[k] = w.y;
    }
    float4 at4 = *(const float4*)&att[4 * l];
    const unsigned long long K02 = pack2(0.2f);

    // 8 src (lanes 0-7) + 8 dst (lanes 8-15), coalesced
    int idxv = 0;
    if (l < 16) idxv = __ldg(&ei[(l < 8 ? 0 : Ee) + base + (l & 7)]);

    int s0 = __shfl_sync(FULLMASK, idxv, 0);
    int dd0 = __shfl_sync(FULLMASK, idxv, 8);
    unsigned long long xl0 = *(const unsigned long long*)&d_xlh[(size_t)s0 * HID + 4 * l];
    unsigned long long xr0 = *(const unsigned long long*)&d_xrh[(size_t)dd0 * HID + 4 * l];

#pragma unroll
    for (int i = 0; i < EPW; i++) {
        // uniform edge-attr load (broadcast; sequential lines)
        const float4* eap = (const float4*)&ea[(size_t)(base + i) * EDC];
        float4 a0 = __ldg(eap);
        float4 a1 = __ldg(eap + 1);

        int s1 = 0, dd1 = 0;
        unsigned long long xl1 = 0ULL, xr1 = 0ULL;
        if (i + 1 < EPW) {  // prefetch next edge's gathers
            s1 = __shfl_sync(FULLMASK, idxv, i + 1);
            dd1 = __shfl_sync(FULLMASK, idxv, 9 + i);
            xl1 = *(const unsigned long long*)&d_xlh[(size_t)s1 * HID + 4 * l];
            xr1 = *(const unsigned long long*)&d_xrh[(size_t)dd1 * HID + 4 * l];
        }

        // ---- compute edge base+i ----
        float2 xla = __half22float2(*(__half2*)&xl0);
        float2 xlb = __half22float2(*((__half2*)&xl0 + 1));
        float2 xra = __half22float2(*(__half2*)&xr0);
        float2 xrb = __half22float2(*((__half2*)&xr0 + 1));
        unsigned long long xlp01 = packxy(xla.x, xla.y);
        unsigned long long xlp23 = packxy(xlb.x, xlb.y);
        unsigned long long s01 = add2(xlp01, packxy(xra.x, xra.y));
        unsigned long long s23 = add2(xlp23, packxy(xrb.x, xrb.y));
        fma2(s01, pack2(a0.x), w01[0]); fma2(s23, pack2(a0.x), w23[0]);
        fma2(s01, pack2(a0.y), w01[1]); fma2(s23, pack2(a0.y), w23[1]);
        fma2(s01, pack2(a0.z), w01[2]); fma2(s23, pack2(a0.z), w23[2]);
        fma2(s01, pack2(a0.w), w01[3]); fma2(s23, pack2(a0.w), w23[3]);
        fma2(s01, pack2(a1.x), w01[4]); fma2(s23, pack2(a1.x), w23[4]);
        fma2(s01, pack2(a1.y), w01[5]); fma2(s23, pack2(a1.y), w23[5]);
        fma2(s01, pack2(a1.z), w01[6]); fma2(s23, pack2(a1.z), w23[6]);
        fma2(s01, pack2(a1.w), w01[7]); fma2(s23, pack2(a1.w), w23[7]);

        // leaky(v) = max(v, 0.2v)
        unsigned long long m01 = mul2(s01, K02);
        unsigned long long m23 = mul2(s23, K02);
        float f0 = fmaxf(lo32(s01), lo32(m01));
        float f1 = fmaxf(hi32(s01), hi32(m01));
        float f2 = fmaxf(lo32(s23), lo32(m23));
        float f3 = fmaxf(hi32(s23), hi32(m23));
        float p = f0 * at4.x;
        p = fmaf(f1, at4.y, p);
        p = fmaf(f2, at4.z, p);
        p = fmaf(f3, at4.w, p);
        p += __shfl_xor_sync(FULLMASK, p, 4);
        p += __shfl_xor_sync(FULLMASK, p, 2);
        p += __shfl_xor_sync(FULLMASK, p, 1);

        float ex = __expf(p);
        if ((l & 7) == 0) red_add_f(&d_den[dd0 * NH + h], ex);
        unsigned long long ex2 = pack2(ex);
        unsigned long long g01 = mul2(xlp01, ex2);
        unsigned long long g23 = mul2(xlp23, ex2);
        // fp16 scatter: 8B per lane instead of 16B
        __half2 h01 = __floats2half2_rn(lo32(g01), hi32(g01));
        __half2 h23 = __floats2half2_rn(lo32(g23), hi32(g23));
        __half* ap = &d_aggh[(size_t)dd0 * HID + 4 * l];
        red_add_h2(ap, *(uint32_t*)&h01);
        red_add_h2(ap + 2, *(uint32_t*)&h23);

        // rotate pipeline
        s0 = s1; dd0 = dd1; xl0 = xl1; xr0 = xr1;
    }
}

// ---------------- epilogue (layer 1): warp-per-node; zeroes aggh/den for layer 2 ----------------
__global__ void __launch_bounds__(256) epi_kernel(
    const float* __restrict__ bo, const float* __restrict__ g,
    const float* __restrict__ beta) {
    int n = blockIdx.x * 8 + (threadIdx.x >> 5);
    int l = threadIdx.x & 31;

    uint2 agr = *(const uint2*)&d_aggh[(size_t)n * HID + 4 * l];
    float2 a01 = __half22float2(*(__half2*)&agr.x);
    float2 a23 = __half22float2(*(__half2*)&agr.y);
    float dn = d_den[n * NH + (l >> 3)];
    float4 z4 = *(const float4*)&d_z[(size_t)n * HID + 4 * l];
    float4 bo4 = *(const float4*)&bo[4 * l];
    float4 g4 = *(const float4*)&g[4 * l];
    float4 bt4 = *(const float4*)&beta[4 * l];

    float inv_dn = (dn > 0.0f) ? __frcp_rn(dn) : 0.0f;
    float4 r;
    r.x = z4.x + fmaxf(fmaf(a01.x, inv_dn, bo4.x), 0.0f);
    r.y = z4.y + fmaxf(fmaf(a01.y, inv_dn, bo4.y), 0.0f);
    r.z = z4.z + fmaxf(fmaf(a23.x, inv_dn, bo4.z), 0.0f);
    r.w = z4.w + fmaxf(fmaf(a23.y, inv_dn, bo4.w), 0.0f);

    // zero for layer 2
    *(uint2*)&d_aggh[(size_t)n * HID + 4 * l] = make_uint2(0u, 0u);
    if (l < NH) d_den[n * NH + l] = 0.0f;

    float s = r.x + r.y + r.z + r.w;
    float q = r.x * r.x + r.y * r.y + r.z * r.z + r.w * r.w;
#pragma unroll
    for (int off = 16; off > 0; off >>= 1) {
        s += __shfl_xor_sync(FULLMASK, s, off);
        q += __shfl_xor_sync(FULLMASK, q, off);
    }
    float mu = s * (1.0f / HID);
    float var = q * (1.0f / HID) - mu * mu;
    float inv = rsqrtf(var + 1e-5f);

    float4 zf;
    zf.x = (r.x - mu) * inv * g4.x + bt4.x;
    zf.y = (r.y - mu) * inv * g4.y + bt4.y;
    zf.z = (r.z - mu) * inv * g4.z + bt4.z;
    zf.w = (r.w - mu) * inv * g4.w + bt4.w;
    *(float4*)&d_z[(size_t)n * HID + 4 * l] = zf;
}

// ---------------- epilogue (layer 2) + fused output head ----------------
__global__ void __launch_bounds__(256) epi_out_kernel(
    const float* __restrict__ bo, const float* __restrict__ g,
    const float* __restrict__ beta, const float* __restrict__ Wout,
    const float* __restrict__ bout, float* __restrict__ out) {
    int n = blockIdx.x * 8 + (threadIdx.x >> 5);
    int l = threadIdx.x & 31;

    uint2 agr = *(const uint2*)&d_aggh[(size_t)n * HID + 4 * l];
    float2 a01 = __half22float2(*(__half2*)&agr.x);
    float2 a23 = __half22float2(*(__half2*)&agr.y);
    float dn = d_den[n * NH + (l >> 3)];
    float4 z4 = *(const float4*)&d_z[(size_t)n * HID + 4 * l];
    float4 bo4 = *(const float4*)&bo[4 * l];
    float4 g4 = *(const float4*)&g[4 * l];
    float4 bt4 = *(const float4*)&beta[4 * l];
    float4 wo4 = *(const float4*)&Wout[4 * l];

    float inv_dn = (dn > 0.0f) ? __frcp_rn(dn) : 0.0f;
    float4 r;
    r.x = z4.x + fmaxf(fmaf(a01.x, inv_dn, bo4.x), 0.0f);
    r.y = z4.y + fmaxf(fmaf(a01.y, inv_dn, bo4.y), 0.0f);
    r.z = z4.z + fmaxf(fmaf(a23.x, inv_dn, bo4.z), 0.0f);
    r.w = z4.w + fmaxf(fmaf(a23.y, inv_dn, bo4.w), 0.0f);

    // no zeroing here — stage0 re-zeroes every call

    float s = r.x + r.y + r.z + r.w;
    float q = r.x * r.x + r.y * r.y + r.z * r.z + r.w * r.w;
#pragma unroll
    for (int off = 16; off > 0; off >>= 1) {
        s += __shfl_xor_sync(FULLMASK, s, off);
        q += __shfl_xor_sync(FULLMASK, q, off);
    }
    float mu = s * (1.0f / HID);
    float var = q * (1.0f / HID) - mu * mu;
    float inv = rsqrtf(var + 1e-5f);

    float4 zf;
    zf.x = (r.x - mu) * inv * g4.x + bt4.x;
    zf.y = (r.y - mu) * inv * g4.y + bt4.y;
    zf.z = (r.z - mu) * inv * g4.z + bt4.z;
    zf.w = (r.w - mu) * inv * g4.w + bt4.w;

    float y = zf.x * wo4.x;
    y = fmaf(zf.y, wo4.y, y);
    y = fmaf(zf.z, wo4.z, y);
    y = fmaf(zf.w, wo4.w, y);
#pragma unroll
    for (int off = 16; off > 0; off >>= 1)
        y += __shfl_xor_sync(FULLMASK, y, off);
    if (l == 0) out[n] = y + __ldg(&bout[0]);
}

// ---------------- launcher ----------------
extern "C" void kernel_launch(void* const* d_in, const int* in_sizes, int n_in,
                              void* d_out, int out_size) {
    const float* x    = (const float*)d_in[0];
    const int*   nidx = (const int*)  d_in[1];
    const int*   ei   = (const int*)  d_in[2];
    const float* ea   = (const float*)d_in[3];
    const float* emb  = (const float*)d_in[4];
    const float* Win  = (const float*)d_in[5];
    const float* bin  = (const float*)d_in[6];
    const float* Wl1  = (const float*)d_in[7];
    const float* bl1  = (const float*)d_in[8];
    const float* Wr1  = (const float*)d_in[9];
    const float* br1  = (const float*)d_in[10];
    const float* We1  = (const float*)d_in[11];
    const float* be1  = (const float*)d_in[12];
    const float* att1 = (const float*)d_in[13];
    const float* bo1  = (const float*)d_in[14];
    const float* Wl2  = (const float*)d_in[15];
    const float* bl2  = (const float*)d_in[16];
    const float* Wr2  = (const float*)d_in[17];
    const float* br2  = (const float*)d_in[18];
    const float* We2  = (const float*)d_in[19];
    const float* be2  = (const float*)d_in[20];
    const float* att2 = (const float*)d_in[21];
    const float* bo2  = (const float*)d_in[22];
    const float* g1   = (const float*)d_in[23];
    const float* beta1= (const float*)d_in[24];
    const float* g2   = (const float*)d_in[25];
    const float* beta2= (const float*)d_in[26];
    const float* Wout = (const float*)d_in[27];
    const float* bout = (const float*)d_in[28];
    float* out = (float*)d_out;

    const int SMEM_PROJ = (64 * PAD + 128 * PAD) * 2;  // 52224 B
    static bool attr_set = false;
    if (!attr_set) {
        cudaFuncSetAttribute(proj_mma_kernel,
                             cudaFuncAttributeMaxDynamicSharedMemorySize, SMEM_PROJ);
        attr_set = true;
    }

    const int PROJ_BLOCKS = (Nn + 63) / 64;   // 782
    const int EDGE_BLOCKS = Ee / (8 * EPW);   // 9375
    const int EPI_BLOCKS = Nn / 8;            // 6250

    stage0_kernel<<<Nn, 128>>>(x, nidx, emb, Win, bin);

    // ---- layer 1 ----
    proj_mma_kernel<<<PROJ_BLOCKS, 256, SMEM_PROJ>>>(Wl1, bl1, Wr1, br1, be1);
    edge_kernel<<<EDGE_BLOCKS, 256>>>(ei, ea, We1, att1);
    epi_kernel<<<EPI_BLOCKS, 256>>>(bo1, g1, beta1);

    // ---- layer 2 ----
    proj_mma_kernel<<<PROJ_BLOCKS, 256, SMEM_PROJ>>>(Wl2, bl2, Wr2, br2, be2);
    edge_kernel<<<EDGE_BLOCKS, 256>>>(ei, ea, We2, att2);
    epi_out_kernel<<<EPI_BLOCKS, 256>>>(bo2, g2, beta2, Wout, bout, out);
}

// round 17
// speedup vs baseline: 1.0212x; 1.0212x over previous
#include <cuda_runtime.h>
#include <cuda_fp16.h>
#include <cstdint>

#define Nn 50000
#define Ee 600000
#define INC 16
#define EDC 8
#define HID 128
#define NH 4
#define CC 32
#define EMBC 64
#define EPW 8
#define FULLMASK 0xffffffffu
#define PAD 136   // halves; 272B row stride -> ldmatrix conflict-free, 16B-aligned rows

// ---------------- scratch (device globals) ----------------
__device__ float d_z[Nn * HID];
__device__ __half d_zh[Nn * HID];    // fp16 mirror of z (proj GEMM input)
__device__ __half d_xlh[Nn * HID];   // fp16; includes +bl
__device__ __half d_xrh[Nn * HID];   // fp16; includes +br+be
__device__ float d_agg[Nn * HID];
__device__ float d_den[Nn * NH];

// packed f32x2 helpers
__device__ __forceinline__ unsigned long long pack2(float a) {
    unsigned long long r;
    asm("mov.b64 %0, {%1, %1};" : "=l"(r) : "r"(__float_as_uint(a)));
    return r;
}
__device__ __forceinline__ unsigned long long packxy(float x, float y) {
    unsigned long long r;
    asm("mov.b64 %0, {%1, %2};" : "=l"(r) : "r"(__float_as_uint(x)), "r"(__float_as_uint(y)));
    return r;
}
__device__ __forceinline__ void fma2(unsigned long long& d, unsigned long long a,
                                     unsigned long long b) {
    asm("fma.rn.f32x2 %0, %1, %2, %0;" : "+l"(d) : "l"(a), "l"(b));
}
__device__ __forceinline__ unsigned long long add2(unsigned long long a,
                                                   unsigned long long b) {
    unsigned long long r;
    asm("add.rn.f32x2 %0, %1, %2;" : "=l"(r) : "l"(a), "l"(b));
    return r;
}
__device__ __forceinline__ unsigned long long mul2(unsigned long long a,
                                                   unsigned long long b) {
    unsigned long long r;
    asm("mul.rn.f32x2 %0, %1, %2;" : "=l"(r) : "l"(a), "l"(b));
    return r;
}
__device__ __forceinline__ float lo32(unsigned long long v) {
    return __uint_as_float((unsigned int)v);
}
__device__ __forceinline__ float hi32(unsigned long long v) {
    return __uint_as_float((unsigned int)(v >> 32));
}
__device__ __forceinline__ void red_add_v4(float* p, float a, float b, float c, float d) {
    asm volatile("red.global.add.v4.f32 [%0], {%1, %2, %3, %4};"
                 :: "l"(p), "f"(a), "f"(b), "f"(c), "f"(d) : "memory");
}
__device__ __forceinline__ void red_add_f(float* p, float a) {
    asm volatile("red.global.add.f32 [%0], %1;" :: "l"(p), "f"(a) : "memory");
}

// ---------------- stage 0: 2 nodes/block; writes z fp32+fp16; zero agg/den ----------------
__global__ void __launch_bounds__(256) stage0_kernel(
    const float* __restrict__ x, const int* __restrict__ nidx,
    const float* __restrict__ emb, const float* __restrict__ Win,
    const float* __restrict__ bin) {
    int n = blockIdx.x * 2 + (threadIdx.x >> 7);
    int t = threadIdx.x & 127;
    float v;
    if (t < EMBC) {
        float a = __ldg(&bin[t]);
#pragma unroll
        for (int k = 0; k < INC; k++)
            a = fmaf(x[n * INC + k], __ldg(&Win[k * EMBC + t]), a);
        v = fmaxf(a, 0.0f);
    } else {
        v = emb[(size_t)nidx[n] * EMBC + (t - EMBC)];
    }
    d_z[(size_t)n * HID + t] = v;
    d_zh[(size_t)n * HID + t] = __float2half_rn(v);
    d_agg[(size_t)n * HID + t] = 0.0f;
    if (t < NH) d_den[n * NH + t] = 0.0f;
}

// ---------------- HMMA projections: A from fp16 z mirror ----------------
__global__ void __launch_bounds__(256) proj_mma_kernel(
    const float* __restrict__ Wl, const float* __restrict__ bl,
    const float* __restrict__ Wr, const float* __restrict__ br,
    const float* __restrict__ be) {
    extern __shared__ char smdyn[];
    __half* zs = (__half*)smdyn;                       // [64][PAD]
    __half* ws = (__half*)(smdyn + 64 * PAD * 2);      // [128][PAD]
    int t = threadIdx.x;
    int w = t >> 5, lane = t & 31;
    int base = blockIdx.x * 64;

    // fill z tile from fp16 mirror: 16B vector copies (1024 chunks of 8 halves)
#pragma unroll
    for (int i = 0; i < 4; i++) {
        int idx = i * 256 + t;
        int r = idx >> 4, c = (idx & 15) * 8;
        int n = base + r;
        if (n >= Nn) n = Nn - 1;
        *(uint4*)&zs[r * PAD + c] = *(const uint4*)&d_zh[(size_t)n * HID + c];
    }

    int sel15 = lane & 15;
    int sel8 = (lane >> 4) << 3;

#pragma unroll
    for (int ph = 0; ph < 2; ph++) {
        const float* W = (ph == 0) ? Wl : Wr;
        if (ph == 1) __syncthreads();
#pragma unroll
        for (int i = 0; i < 64; i++) {
            int idx = i * 256 + t;
            int k = idx >> 7, n = idx & 127;
            ws[k * PAD + n] = __float2half_rn(__ldg(&W[k * HID + n]));
        }
        __syncthreads();

        float acc[4][2][4];
#pragma unroll
        for (int mt = 0; mt < 4; mt++)
#pragma unroll
            for (int nt = 0; nt < 2; nt++)
#pragma unroll
                for (int j = 0; j < 4; j++) acc[mt][nt][j] = 0.0f;

#pragma unroll
        for (int ks = 0; ks < 8; ks++) {
            uint32_t b0, b1, b2, b3;
            {
                int krow = ks * 16 + sel15;
                int ncol = 16 * w + sel8;
                uint32_t ad = (uint32_t)__cvta_generic_to_shared(&ws[krow * PAD + ncol]);
                asm volatile("ldmatrix.sync.aligned.m8n8.x4.trans.shared.b16 {%0,%1,%2,%3}, [%4];"
                             : "=r"(b0), "=r"(b1), "=r"(b2), "=r"(b3) : "r"(ad));
            }
#pragma unroll
            for (int mt = 0; mt < 4; mt++) {
                uint32_t a0, a1, a2, a3;
                int arow = mt * 16 + sel15;
                int acol = ks * 16 + sel8;
                uint32_t ad = (uint32_t)__cvta_generic_to_shared(&zs[arow * PAD + acol]);
                asm volatile("ldmatrix.sync.aligned.m8n8.x4.shared.b16 {%0,%1,%2,%3}, [%4];"
                             : "=r"(a0), "=r"(a1), "=r"(a2), "=r"(a3) : "r"(ad));
                asm volatile("mma.sync.aligned.m16n8k16.row.col.f32.f16.f16.f32 "
                             "{%0,%1,%2,%3}, {%4,%5,%6,%7}, {%8,%9}, {%0,%1,%2,%3};"
                             : "+f"(acc[mt][0][0]), "+f"(acc[mt][0][1]),
                               "+f"(acc[mt][0][2]), "+f"(acc[mt][0][3])
                             : "r"(a0), "r"(a1), "r"(a2), "r"(a3), "r"(b0), "r"(b1));
                asm volatile("mma.sync.aligned.m16n8k16.row.col.f32.f16.f16.f32 "
                             "{%0,%1,%2,%3}, {%4,%5,%6,%7}, {%8,%9}, {%0,%1,%2,%3};"
                             : "+f"(acc[mt][1][0]), "+f"(acc[mt][1][1]),
                               "+f"(acc[mt][1][2]), "+f"(acc[mt][1][3])
                             : "r"(a0), "r"(a1), "r"(a2), "r"(a3), "r"(b2), "r"(b3));
            }
        }

        __half* dst = (ph == 0) ? d_xlh : d_xrh;
#pragma unroll
        for (int nt = 0; nt < 2; nt++) {
            int col = 16 * w + nt * 8 + (lane & 3) * 2;
            float bv0, bv1;
            if (ph == 0) {
                bv0 = __ldg(&bl[col]);
                bv1 = __ldg(&bl[col + 1]);
            } else {
                bv0 = __ldg(&br[col]) + __ldg(&be[col]);
                bv1 = __ldg(&br[col + 1]) + __ldg(&be[col + 1]);
            }
#pragma unroll
            for (int mt = 0; mt < 4; mt++) {
                int r0 = base + mt * 16 + (lane >> 2);
                int r1 = r0 + 8;
                if (r0 < Nn) {
                    __half2 v = __floats2half2_rn(acc[mt][nt][0] + bv0, acc[mt][nt][1] + bv1);
                    *(__half2*)&dst[(size_t)r0 * HID + col] = v;
                }
                if (r1 < Nn) {
                    __half2 v = __floats2half2_rn(acc[mt][nt][2] + bv0, acc[mt][nt][3] + bv1);
                    *(__half2*)&dst[(size_t)r1 * HID + col] = v;
                }
            }
        }
    }
}

// ---------------- fused edge pass: logit -> exp -> den + weighted agg (fp32 red.v4) ----------------
__global__ void __launch_bounds__(256, 4) edge_kernel(
    const int* __restrict__ ei, const float* __restrict__ ea,
    const float* __restrict__ We, const float* __restrict__ att) {
    int l = threadIdx.x & 31;
    int warp = (blockIdx.x * blockDim.x + threadIdx.x) >> 5;
    int base = warp * EPW;
    if (base >= Ee) return;
    int h = l >> 3;

    unsigned long long w01[EDC], w23[EDC];
#pragma unroll
    for (int k = 0; k < EDC; k++) {
        ulonglong2 w = *(const ulonglong2*)&We[k * HID + 4 * l];
        w01[k] = w.x;
        w23[k] = w.y;
    }
    float4 at4 = *(const float4*)&att[4 * l];
    const unsigned long long K02 = pack2(0.2f);

    // 8 src (lanes 0-7) + 8 dst (lanes 8-15), coalesced
    int idxv = 0;
    if (l < 16) idxv = __ldg(&ei[(l < 8 ? 0 : Ee) + base + (l & 7)]);

    int s0 = __shfl_sync(FULLMASK, idxv, 0);
    int dd0 = __shfl_sync(FULLMASK, idxv, 8);
    unsigned long long xl0 = *(const unsigned long long*)&d_xlh[(size_t)s0 * HID + 4 * l];
    unsigned long long xr0 = *(const unsigned long long*)&d_xrh[(size_t)dd0 * HID + 4 * l];

#pragma unroll
    for (int i = 0; i < EPW; i++) {
        // uniform edge-attr load (broadcast; sequential lines)
        const float4* eap = (const float4*)&ea[(size_t)(base + i) * EDC];
        float4 a0 = __ldg(eap);
        float4 a1 = __ldg(eap + 1);

        int s1 = 0, dd1 = 0;
        unsigned long long xl1 = 0ULL, xr1 = 0ULL;
        if (i + 1 < EPW) {  // prefetch next edge's gathers
            s1 = __shfl_sync(FULLMASK, idxv, i + 1);
            dd1 = __shfl_sync(FULLMASK, idxv, 9 + i);
            xl1 = *(const unsigned long long*)&d_xlh[(size_t)s1 * HID + 4 * l];
            xr1 = *(const unsigned long long*)&d_xrh[(size_t)dd1 * HID + 4 * l];
        }

        // ---- compute edge base+i ----
        float2 xla = __half22float2(*(__half2*)&xl0);
        float2 xlb = __half22float2(*((__half2*)&xl0 + 1));
        float2 xra = __half22float2(*(__half2*)&xr0);
        float2 xrb = __half22float2(*((__half2*)&xr0 + 1));
        unsigned long long xlp01 = packxy(xla.x, xla.y);
        unsigned long long xlp23 = packxy(xlb.x, xlb.y);
        unsigned long long s01 = add2(xlp01, packxy(xra.x, xra.y));
        unsigned long long s23 = add2(xlp23, packxy(xrb.x, xrb.y));
        fma2(s01, pack2(a0.x), w01[0]); fma2(s23, pack2(a0.x), w23[0]);
        fma2(s01, pack2(a0.y), w01[1]); fma2(s23, pack2(a0.y), w23[1]);
        fma2(s01, pack2(a0.z), w01[2]); fma2(s23, pack2(a0.z), w23[2]);
        fma2(s01, pack2(a0.w), w01[3]); fma2(s23, pack2(a0.w), w23[3]);
        fma2(s01, pack2(a1.x), w01[4]); fma2(s23, pack2(a1.x), w23[4]);
        fma2(s01, pack2(a1.y), w01[5]); fma2(s23, pack2(a1.y), w23[5]);
        fma2(s01, pack2(a1.z), w01[6]); fma2(s23, pack2(a1.z), w23[6]);
        fma2(s01, pack2(a1.w), w01[7]); fma2(s23, pack2(a1.w), w23[7]);

        // leaky(v) = max(v, 0.2v)
        unsigned long long m01 = mul2(s01, K02);
        unsigned long long m23 = mul2(s23, K02);
        float f0 = fmaxf(lo32(s01), lo32(m01));
        float f1 = fmaxf(hi32(s01), hi32(m01));
        float f2 = fmaxf(lo32(s23), lo32(m23));
        float f3 = fmaxf(hi32(s23), hi32(m23));
        float p = f0 * at4.x;
        p = fmaf(f1, at4.y, p);
        p = fmaf(f2, at4.z, p);
        p = fmaf(f3, at4.w, p);
        p += __shfl_xor_sync(FULLMASK, p, 4);
        p += __shfl_xor_sync(FULLMASK, p, 2);
        p += __shfl_xor_sync(FULLMASK, p, 1);

        float ex = __expf(p);
        if ((l & 7) == 0) red_add_f(&d_den[dd0 * NH + h], ex);
        unsigned long long ex2 = pack2(ex);
        unsigned long long g01 = mul2(xlp01, ex2);
        unsigned long long g23 = mul2(xlp23, ex2);
        red_add_v4(&d_agg[(size_t)dd0 * HID + 4 * l],
                   lo32(g01), hi32(g01), lo32(g23), hi32(g23));

        // rotate pipeline
        s0 = s1; dd0 = dd1; xl0 = xl1; xr0 = xr1;
    }
}

// ---------------- epilogue (layer 1): warp-per-node; writes z fp32+fp16; zeroes agg/den ----------------
__global__ void __launch_bounds__(256) epi_kernel(
    const float* __restrict__ bo, const float* __restrict__ g,
    const float* __restrict__ beta) {
    int n = blockIdx.x * 8 + (threadIdx.x >> 5);
    int l = threadIdx.x & 31;

    float4 ag = *(const float4*)&d_agg[(size_t)n * HID + 4 * l];
    float dn = d_den[n * NH + (l >> 3)];
    float4 z4 = *(const float4*)&d_z[(size_t)n * HID + 4 * l];
    float4 bo4 = *(const float4*)&bo[4 * l];
    float4 g4 = *(const float4*)&g[4 * l];
    float4 bt4 = *(const float4*)&beta[4 * l];

    float inv_dn = (dn > 0.0f) ? __frcp_rn(dn) : 0.0f;
    float4 r;
    r.x = z4.x + fmaxf(fmaf(ag.x, inv_dn, bo4.x), 0.0f);
    r.y = z4.y + fmaxf(fmaf(ag.y, inv_dn, bo4.y), 0.0f);
    r.z = z4.z + fmaxf(fmaf(ag.z, inv_dn, bo4.z), 0.0f);
    r.w = z4.w + fmaxf(fmaf(ag.w, inv_dn, bo4.w), 0.0f);

    *(float4*)&d_agg[(size_t)n * HID + 4 * l] = make_float4(0.f, 0.f, 0.f, 0.f);
    if (l < NH) d_den[n * NH + l] = 0.0f;

    float s = r.x + r.y + r.z + r.w;
    float q = r.x * r.x + r.y * r.y + r.z * r.z + r.w * r.w;
#pragma unroll
    for (int off = 16; off > 0; off >>= 1) {
        s += __shfl_xor_sync(FULLMASK, s, off);
        q += __shfl_xor_sync(FULLMASK, q, off);
    }
    float mu = s * (1.0f / HID);
    float var = q * (1.0f / HID) - mu * mu;
    float inv = rsqrtf(var + 1e-5f);

    float4 zf;
    zf.x = (r.x - mu) * inv * g4.x + bt4.x;
    zf.y = (r.y - mu) * inv * g4.y + bt4.y;
    zf.z = (r.z - mu) * inv * g4.z + bt4.z;
    zf.w = (r.w - mu) * inv * g4.w + bt4.w;
    *(float4*)&d_z[(size_t)n * HID + 4 * l] = zf;
    // fp16 mirror for layer-2 proj (4 halves = 8 bytes = uint2)
    __half2 m0 = __floats2half2_rn(zf.x, zf.y);
    __half2 m1 = __floats2half2_rn(zf.z, zf.w);
    *(uint2*)&d_zh[(size_t)n * HID + 4 * l] =
        make_uint2(*(uint32_t*)&m0, *(uint32_t*)&m1);
}

// ---------------- epilogue (layer 2) + fused output head ----------------
__global__ void __launch_bounds__(256) epi_out_kernel(
    const float* __restrict__ bo, const float* __restrict__ g,
    const float* __restrict__ beta, const float* __restrict__ Wout,
    const float* __restrict__ bout, float* __restrict__ out) {
    int n = blockIdx.x * 8 + (threadIdx.x >> 5);
    int l = threadIdx.x & 31;

    float4 ag = *(const float4*)&d_agg[(size_t)n * HID + 4 * l];
    float dn = d_den[n * NH + (l >> 3)];
    float4 z4 = *(const float4*)&d_z[(size_t)n * HID + 4 * l];
    float4 bo4 = *(const float4*)&bo[4 * l];
    float4 g4 = *(const float4*)&g[4 * l];
    float4 bt4 = *(const float4*)&beta[4 * l];
    float4 wo4 = *(const float4*)&Wout[4 * l];

    float inv_dn = (dn > 0.0f) ? __frcp_rn(dn) : 0.0f;
    float4 r;
    r.x = z4.x + fmaxf(fmaf(ag.x, inv_dn, bo4.x), 0.0f);
    r.y = z4.y + fmaxf(fmaf(ag.y, inv_dn, bo4.y), 0.0f);
    r.z = z4.z + fmaxf(fmaf(ag.z, inv_dn, bo4.z), 0.0f);
    r.w = z4.w + fmaxf(fmaf(ag.w, inv_dn, bo4.w), 0.0f);

    // no zeroing here — stage0 re-zeroes every call

    float s = r.x + r.y + r.z + r.w;
    float q = r.x * r.x + r.y * r.y + r.z * r.z + r.w * r.w;
#pragma unroll
    for (int off = 16; off > 0; off >>= 1) {
        s += __shfl_xor_sync(FULLMASK, s, off);
        q += __shfl_xor_sync(FULLMASK, q, off);
    }
    float mu = s * (1.0f / HID);
    float var = q * (1.0f / HID) - mu * mu;
    float inv = rsqrtf(var + 1e-5f);

    float4 zf;
    zf.x = (r.x - mu) * inv * g4.x + bt4.x;
    zf.y = (r.y - mu) * inv * g4.y + bt4.y;
    zf.z = (r.z - mu) * inv * g4.z + bt4.z;
    zf.w = (r.w - mu) * inv * g4.w + bt4.w;

    float y = zf.x * wo4.x;
    y = fmaf(zf.y, wo4.y, y);
    y = fmaf(zf.z, wo4.z, y);
    y = fmaf(zf.w, wo4.w, y);
#pragma unroll
    for (int off = 16; off > 0; off >>= 1)
        y += __shfl_xor_sync(FULLMASK, y, off);
    if (l == 0) out[n] = y + __ldg(&bout[0]);
}

// ---------------- launcher ----------------
extern "C" void kernel_launch(void* const* d_in, const int* in_sizes, int n_in,
                              void* d_out, int out_size) {
    const float* x    = (const float*)d_in[0];
    const int*   nidx = (const int*)  d_in[1];
    const int*   ei   = (const int*)  d_in[2];
    const float* ea   = (const float*)d_in[3];
    const float* emb  = (const float*)d_in[4];
    const float* Win  = (const float*)d_in[5];
    const float* bin  = (const float*)d_in[6];
    const float* Wl1  = (const float*)d_in[7];
    const float* bl1  = (const float*)d_in[8];
    const float* Wr1  = (const float*)d_in[9];
    const float* br1  = (const float*)d_in[10];
    const float* We1  = (const float*)d_in[11];
    const float* be1  = (const float*)d_in[12];
    const float* att1 = (const float*)d_in[13];
    const float* bo1  = (const float*)d_in[14];
    const float* Wl2  = (const float*)d_in[15];
    const float* bl2  = (const float*)d_in[16];
    const float* Wr2  = (const float*)d_in[17];
    const float* br2  = (const float*)d_in[18];
    const float* We2  = (const float*)d_in[19];
    const float* be2  = (const float*)d_in[20];
    const float* att2 = (const float*)d_in[21];
    const float* bo2  = (const float*)d_in[22];
    const float* g1   = (const float*)d_in[23];
    const float* beta1= (const float*)d_in[24];
    const float* g2   = (const float*)d_in[25];
    const float* beta2= (const float*)d_in[26];
    const float* Wout = (const float*)d_in[27];
    const float* bout = (const float*)d_in[28];
    float* out = (float*)d_out;

    const int SMEM_PROJ = (64 * PAD + 128 * PAD) * 2;  // 52224 B
    static bool attr_set = false;
    if (!attr_set) {
        cudaFuncSetAttribute(proj_mma_kernel,
                             cudaFuncAttributeMaxDynamicSharedMemorySize, SMEM_PROJ);
        attr_set = true;
    }

    const int PROJ_BLOCKS = (Nn + 63) / 64;   // 782
    const int EDGE_BLOCKS = Ee / (8 * EPW);   // 9375
    const int EPI_BLOCKS = Nn / 8;            // 6250

    stage0_kernel<<<Nn / 2, 256>>>(x, nidx, emb, Win, bin);

    // ---- layer 1 ----
    proj_mma_kernel<<<PROJ_BLOCKS, 256, SMEM_PROJ>>>(Wl1, bl1, Wr1, br1, be1);
    edge_kernel<<<EDGE_BLOCKS, 256>>>(ei, ea, We1, att1);
    epi_kernel<<<EPI_BLOCKS, 256>>>(bo1, g1, beta1);

    // ---- layer 2 ----
    proj_mma_kernel<<<PROJ_BLOCKS, 256, SMEM_PROJ>>>(Wl2, bl2, Wr2, br2, be2);
    edge_kernel<<<EDGE_BLOCKS, 256>>>(ei, ea, We2, att2);
    epi_out_kernel<<<EPI_BLOCKS, 256>>>(bo2, g2, beta2, Wout, bout, out);
}